// round 8
// baseline (speedup 1.0000x reference)
#include <cuda_runtime.h>
#include <math_constants.h>

#define NN  1024
#define VV  32000
#define BB  16
#define TT  128
#define GG  128            // forward CTAs: 8 clusters/groups x 16 CTAs
#define NGRP 8
#define GSZ  16            // CTAs per group/cluster
#define RR  (NN/GSZ)       // 64 rows of E_T per CTA
#define GB  2              // batches per group
#define TPB 256

// ---------------- device scratch (static; no runtime alloc) ----------------
__device__ unsigned short d_ETh[NN*NN];       // bf16 exp(log_T' - rowmax), 2 MB
__device__ float          d_rowmax[NN];
__device__ float          d_rowlse[NN];
__device__ float          d_collse[NN];
__device__ float          d_piadj[NN];        // log_pi - rowmax
__device__ float          d_emitg[TT*BB*NN];  // emit - rowlse + rowmax, [t][b][m]
__device__ unsigned short d_eag[2][BB*NN];    // fallback path: bf16 ea ping-pong
__device__ float          d_easum[TT*BB];     // sum_n ea per (t,b) history
__device__ float          d_shift[TT*BB];     // shift used per (t,b) history
__device__ unsigned       d_gcnt[NGRP];       // fallback path: group counters

// ---------------- helpers ----------------
__device__ __forceinline__ unsigned long long ffma2(
    unsigned long long a, unsigned long long b, unsigned long long c) {
    unsigned long long d;
    asm("fma.rn.f32x2 %0, %1, %2, %3;" : "=l"(d) : "l"(a), "l"(b), "l"(c));
    return d;
}
__device__ __forceinline__ unsigned long long bf2f32x2(unsigned u) {
    unsigned lo = u << 16, hi = u & 0xffff0000u;
    unsigned long long p;
    asm("mov.b64 %0, {%1,%2};" : "=l"(p) : "r"(lo), "r"(hi));
    return p;
}
__device__ __forceinline__ void cp_async16(unsigned dst_smem, const void* src) {
    asm volatile("cp.async.cg.shared.global [%0], [%1], 16;"
                 :: "r"(dst_smem), "l"(src));
}
__device__ __forceinline__ unsigned bf16x2pack(float lo, float hi) {
    unsigned r;
    asm("cvt.rn.bf16x2.f32 %0, %1, %2;" : "=r"(r) : "f"(hi), "f"(lo));
    return r;
}
__device__ __forceinline__ unsigned mapa_rank(unsigned addr, int rank) {
    unsigned r;
    asm("mapa.shared::cluster.u32 %0, %1, %2;" : "=r"(r) : "r"(addr), "r"(rank));
    return r;
}
__device__ __forceinline__ void st_cluster_u32(unsigned addr, unsigned v) {
    asm volatile("st.shared::cluster.u32 [%0], %1;" :: "r"(addr), "r"(v));
}
__device__ __forceinline__ void cluster_arrive() {
    asm volatile("barrier.cluster.arrive.aligned;" ::: "memory");
}
__device__ __forceinline__ void cluster_wait() {
    asm volatile("barrier.cluster.wait.aligned;" ::: "memory");
}

// fallback group barrier (proven R7)
__device__ __forceinline__ void gbar(unsigned* cnt, unsigned target) {
    __syncthreads();
    if (threadIdx.x == 0) {
        asm volatile("red.release.gpu.add.u32 [%0], 1;" :: "l"(cnt));
        unsigned v;
        do {
            asm volatile("ld.acquire.gpu.u32 %0, [%1];" : "=r"(v) : "l"(cnt));
        } while (v < target);
    }
    __syncthreads();
}

// ---------------- prep kernels ----------------
__global__ void k_rowlse(const float* __restrict__ emis) {
    int n = blockIdx.x;
    const float* row = emis + (size_t)n * VV;
    float mx = -CUDART_INF_F, s = 0.f;
    for (int i = threadIdx.x; i < VV; i += TPB) {
        float v = row[i];
        if (v > mx) { s = s * __expf(mx - v) + 1.f; mx = v; }
        else        { s += __expf(v - mx); }
    }
    __shared__ float smx[TPB], ss[TPB];
    smx[threadIdx.x] = mx; ss[threadIdx.x] = s;
    __syncthreads();
    for (int off = TPB / 2; off; off >>= 1) {
        if (threadIdx.x < off) {
            float m1 = smx[threadIdx.x], s1 = ss[threadIdx.x];
            float m2 = smx[threadIdx.x + off], s2 = ss[threadIdx.x + off];
            float m = fmaxf(m1, m2);
            ss[threadIdx.x]  = s1 * __expf(m1 - m) + s2 * __expf(m2 - m);
            smx[threadIdx.x] = m;
        }
        __syncthreads();
    }
    if (threadIdx.x == 0) d_rowlse[n] = smx[0] + __logf(ss[0]);
}

__global__ void k_collse(const float* __restrict__ trans) {
    int col = blockIdx.x * 32 + threadIdx.x;
    int ty  = threadIdx.y;
    float mx = -CUDART_INF_F, s = 0.f;
    for (int m = ty; m < NN; m += 8) {
        float v = trans[m * NN + col];
        if (v > mx) { s = s * __expf(mx - v) + 1.f; mx = v; }
        else        { s += __expf(v - mx); }
    }
    __shared__ float smx[8][32], ss[8][32];
    smx[ty][threadIdx.x] = mx; ss[ty][threadIdx.x] = s;
    __syncthreads();
    if (ty == 0) {
        float m1 = mx, s1 = s;
        for (int j = 1; j < 8; j++) {
            float m2 = smx[j][threadIdx.x], s2 = ss[j][threadIdx.x];
            float m = fmaxf(m1, m2);
            s1 = s1 * __expf(m1 - m) + s2 * __expf(m2 - m);
            m1 = m;
        }
        d_collse[col] = m1 + __logf(s1);
    }
}

__global__ void k_prepT(const float* __restrict__ trans) {
    int m = blockIdx.x;
    const float* rowp = trans + (size_t)m * NN;
    float mx = -CUDART_INF_F;
    for (int n = threadIdx.x; n < NN; n += TPB)
        mx = fmaxf(mx, rowp[n] - d_collse[n]);
    __shared__ float smx[TPB];
    smx[threadIdx.x] = mx; __syncthreads();
    for (int off = TPB / 2; off; off >>= 1) {
        if (threadIdx.x < off)
            smx[threadIdx.x] = fmaxf(smx[threadIdx.x], smx[threadIdx.x + off]);
        __syncthreads();
    }
    float rm = smx[0];
    if (threadIdx.x == 0) d_rowmax[m] = rm;
    for (int n = threadIdx.x; n < NN; n += TPB) {
        float e = __expf(rowp[n] - d_collse[n] - rm);
        unsigned r;
        asm("cvt.rn.bf16x2.f32 %0, %1, %2;" : "=r"(r) : "f"(0.f), "f"(e));
        d_ETh[m * NN + n] = (unsigned short)(r & 0xffffu);
    }
}

__global__ void k_init(const float* __restrict__ pri) {
    int base = blockIdx.x * 128;
    if (threadIdx.x < 128) d_easum[base + threadIdx.x] = 0.f;
    if (blockIdx.x == 0) {
        if (threadIdx.x < NGRP) d_gcnt[threadIdx.x] = 0u;
        float mx = -CUDART_INF_F, s = 0.f;
        for (int i = threadIdx.x; i < NN; i += TPB) {
            float v = pri[i];
            if (v > mx) { s = s * __expf(mx - v) + 1.f; mx = v; }
            else        { s += __expf(v - mx); }
        }
        __shared__ float smx[TPB], ss[TPB];
        smx[threadIdx.x] = mx; ss[threadIdx.x] = s;
        __syncthreads();
        for (int off = TPB / 2; off; off >>= 1) {
            if (threadIdx.x < off) {
                float m1 = smx[threadIdx.x], s1 = ss[threadIdx.x];
                float m2 = smx[threadIdx.x + off], s2 = ss[threadIdx.x + off];
                float m = fmaxf(m1, m2);
                ss[threadIdx.x]  = s1 * __expf(m1 - m) + s2 * __expf(m2 - m);
                smx[threadIdx.x] = m;
            }
            __syncthreads();
        }
        __shared__ float lp;
        if (threadIdx.x == 0) lp = smx[0] + __logf(ss[0]);
        __syncthreads();
        for (int m = threadIdx.x; m < NN; m += TPB)
            d_piadj[m] = pri[m] - lp - d_rowmax[m];
    }
}

// emitg[t][b][m]
__global__ void k_gather(const float* __restrict__ emis, const int* __restrict__ x) {
    int t = blockIdx.x;
    __shared__ int tok[BB];
    if (threadIdx.x < BB) tok[threadIdx.x] = x[threadIdx.x * TT + t];
    __syncthreads();
    float* dst = d_emitg + (size_t)t * BB * NN;
    for (int i = threadIdx.x; i < BB * NN; i += TPB) {
        int b = i >> 10, m = i & (NN - 1);
        dst[i] = __ldg(&emis[(size_t)m * VV + tok[b]]) - d_rowlse[m] + d_rowmax[m];
    }
}

// =============== CLUSTER forward kernel (primary path) ======================
// dyn smem: E 128KB | ea2 2x4KB | eaw 256B | psum 2x128B | alpha 512B
#define EA2_OFF  (RR*NN*2)
#define EAW_OFF  (EA2_OFF + 2*GB*NN*2)
#define PS_OFF   (EAW_OFF + 64*4)
#define AL_OFF   (PS_OFF + 2*GSZ*GB*4)
#define CL_SMEM  (AL_OFF + RR*GB*4)

__global__ void __launch_bounds__(TPB, 1)
k_fwd_cl(const int* __restrict__ len, float* __restrict__ out) {
    extern __shared__ char sh[];
    char*     E_shb    = sh;
    char*     ea2      = sh + EA2_OFF;
    unsigned* eaw      = (unsigned*)(sh + EAW_OFF);
    float*    psum     = (float*)(sh + PS_OFF);      // [2][GSZ][GB]
    float*    alpha_sh = (float*)(sh + AL_OFF);      // [RR][GB]
    __shared__ float sA[GB], sB[GB], wsum[8], lsum[GB];

    const int tid = threadIdx.x;
    const int w = tid >> 5, lane = tid & 31;
    unsigned ci_u;
    asm("mov.u32 %0, %%cluster_ctarank;" : "=r"(ci_u));
    const int ci = (int)ci_u;
    const int gg = blockIdx.x >> 4;
    const int b0 = gg * GB;
    const unsigned smem_u = (unsigned)__cvta_generic_to_shared(sh);

    // stage E_T rows [ci*RR, ci*RR+RR)
    {
        const uint4* src = (const uint4*)(d_ETh + (size_t)ci * RR * NN);
        uint4* dst = (uint4*)E_shb;
        for (int i = tid; i < RR * NN * 2 / 16; i += TPB) dst[i] = src[i];
    }
    if (tid < GB) { sA[tid] = 0.f; sB[tid] = 0.f; }
    float sPrev = 0.f, lseP = 0.f;         // valid in tid<GB threads
    __syncthreads();

    const int b_f = tid >> 6, r_f = tid & 63;
    const int m_f = ci * RR + r_f;

    for (int t = 0; t < TT; t++) {
        // prefetch emit for this step
        float em = 0.f, pa = 0.f;
        if (tid < 128) {
            em = __ldcg(&d_emitg[((size_t)t * BB + (b0 + b_f)) * NN + m_f]);
            if (t == 0) pa = __ldcg(&d_piadj[m_f]);
        }

        if (t > 0) cluster_wait();         // exchange(t-1) complete (acquire)

        // shift(t) from exact lse(t-1) (psum totals now local)
        if (tid < GB) {
            float sh_t = 0.f;
            if (t >= 1) {
                const float* ps = psum + ((t - 1) & 1) * (GSZ * GB);
                float tot = 0.f;
#pragma unroll
                for (int r = 0; r < GSZ; r++) tot += ps[r * GB + tid];
                float lse = sPrev + __logf(tot);
                float d = (t >= 2) ? fminf(20.f, fmaxf(-40.f, lse - lseP)) : 0.f;
                sh_t = lse + d;
                lseP = lse;
                if (ci == 0) d_easum[(t - 1) * BB + b0 + tid] = tot;
            }
            sA[tid] = sPrev;
            sB[tid] = sh_t;
            sPrev = sh_t;
            if (ci == 0) d_shift[t * BB + b0 + tid] = sh_t;
        }

        // matvec on local ea buffer (t-1 parity)
        if (t > 0) {
            const char* ea_rd = ea2 + ((t - 1) & 1) * (GB * NN * 2);
            unsigned long long acc[8][GB];
#pragma unroll
            for (int j = 0; j < 8; j++)
#pragma unroll
                for (int k = 0; k < GB; k++) acc[j][k] = 0ull;
#pragma unroll
            for (int c = 0; c < 4; c++) {
                int n0 = c * 256 + lane * 8;
                uint4 av0 = *(const uint4*)(ea_rd + n0 * 2);
                uint4 av1 = *(const uint4*)(ea_rd + (NN + n0) * 2);
                unsigned long long a0[4], a1[4];
                a0[0] = bf2f32x2(av0.x); a0[1] = bf2f32x2(av0.y);
                a0[2] = bf2f32x2(av0.z); a0[3] = bf2f32x2(av0.w);
                a1[0] = bf2f32x2(av1.x); a1[1] = bf2f32x2(av1.y);
                a1[2] = bf2f32x2(av1.z); a1[3] = bf2f32x2(av1.w);
#pragma unroll
                for (int j = 0; j < 8; j++) {
                    uint4 ev = *(const uint4*)
                        (E_shb + ((w * 8 + j) * NN + n0) * 2);
                    unsigned long long e0 = bf2f32x2(ev.x), e1 = bf2f32x2(ev.y);
                    unsigned long long e2 = bf2f32x2(ev.z), e3 = bf2f32x2(ev.w);
                    acc[j][0] = ffma2(e0, a0[0], acc[j][0]);
                    acc[j][0] = ffma2(e1, a0[1], acc[j][0]);
                    acc[j][0] = ffma2(e2, a0[2], acc[j][0]);
                    acc[j][0] = ffma2(e3, a0[3], acc[j][0]);
                    acc[j][1] = ffma2(e0, a1[0], acc[j][1]);
                    acc[j][1] = ffma2(e1, a1[1], acc[j][1]);
                    acc[j][1] = ffma2(e2, a1[2], acc[j][1]);
                    acc[j][1] = ffma2(e3, a1[3], acc[j][1]);
                }
            }
            float r[8][GB];
#pragma unroll
            for (int j = 0; j < 8; j++)
#pragma unroll
                for (int k = 0; k < GB; k++) {
                    float2 f = *(float2*)&acc[j][k];
                    r[j][k] = f.x + f.y;
                }
#pragma unroll
            for (int off = 16; off; off >>= 1)
#pragma unroll
                for (int j = 0; j < 8; j++)
#pragma unroll
                    for (int k = 0; k < GB; k++)
                        r[j][k] += __shfl_xor_sync(0xffffffffu, r[j][k], off);
            if (lane == 0) {
#pragma unroll
                for (int j = 0; j < 8; j++)
#pragma unroll
                    for (int k = 0; k < GB; k++)
                        alpha_sh[(w * 8 + j) * GB + k] = r[j][k];
            }
        }
        __syncthreads();   // alpha + sA/sB

        // finalize -> ea words into staging + warp sums
        if (tid < 128) {
            float A = (t == 0)
                ? (em + pa)
                : (em + sA[b_f] + __logf(alpha_sh[r_f * GB + b_f]));
            float e = __expf(A - sB[b_f]);
            float e1 = __shfl_down_sync(0xffffffffu, e, 1);
            if (!(tid & 1))
                eaw[b_f * 32 + (r_f >> 1)] = bf16x2pack(e, e1);
            float sm = e;
#pragma unroll
            for (int off = 16; off; off >>= 1)
                sm += __shfl_xor_sync(0xffffffffu, sm, off);
            if (lane == 0) wsum[w] = sm;
        }
        __syncthreads();
        if (tid < GB) lsum[tid] = wsum[2 * tid] + wsum[2 * tid + 1];
        __syncthreads();

        // DSMEM broadcast of ea slice + partial sums to all 16 ranks
        {
            unsigned eabuf = smem_u + EA2_OFF + (unsigned)((t & 1) * (GB * NN * 2));
#pragma unroll
            for (int it = 0; it < 4; it++) {
                int flat = tid + 256 * it;           // [0,1024)
                int rank = flat >> 6, word = flat & 63;
                int b = word >> 5, j = word & 31;
                unsigned laddr = eabuf +
                    (unsigned)((b * (NN / 2) + ci * (RR / 2) + j) * 4);
                st_cluster_u32(mapa_rank(laddr, rank), eaw[word]);
            }
            if (tid < 2 * GSZ) {
                int rank = tid >> 1, b = tid & 1;
                unsigned laddr = smem_u + PS_OFF +
                    (unsigned)((t & 1) * (GSZ * GB) * 4 + (ci * GB + b) * 4);
                st_cluster_u32(mapa_rank(laddr, rank),
                               __float_as_uint(lsum[b]));
            }
        }
        cluster_arrive();                  // release prior cluster stores
    }

    cluster_wait();                        // match final arrive

    // group-local output (ci==0 wrote all history itself)
    if (ci == 0) {
        if (tid < GB) {
            const float* ps = psum + ((TT - 1) & 1) * (GSZ * GB);
            float tot = 0.f;
#pragma unroll
            for (int r = 0; r < GSZ; r++) tot += ps[r * GB + tid];
            d_easum[(TT - 1) * BB + b0 + tid] = tot;
            int b = b0 + tid;
            int tb = len[b] - 1;
            tb = tb < 0 ? 0 : (tb > TT - 1 ? TT - 1 : tb);
            out[b] = d_shift[tb * BB + b] + __logf(d_easum[tb * BB + b]);
        }
    }
}

// =============== fallback forward kernel (proven R7 path) ===================
#define FB_SMEM (RR*NN*2 + GB*NN*2 + (RR*GB + 8)*4)

__global__ void __launch_bounds__(TPB, 1)
k_fwd_fb(const int* __restrict__ len, float* __restrict__ out) {
    extern __shared__ char sh[];
    char*  E_shb    = sh;
    char*  ea_sh    = sh + RR * NN * 2;
    float* alpha_sh = (float*)(ea_sh + GB * NN * 2);
    float* wsum     = alpha_sh + RR * GB;
    __shared__ float sA[GB], sB[GB];

    const int g = blockIdx.x, tid = threadIdx.x;
    const int w = tid >> 5, lane = tid & 31;
    const int gg = g >> 4, ci = g & 15, b0 = gg * GB;
    unsigned* cnt = &d_gcnt[gg];
    const unsigned ea_smem = (unsigned)__cvta_generic_to_shared(ea_sh);

    {
        const uint4* src = (const uint4*)(d_ETh + (size_t)ci * RR * NN);
        uint4* dst = (uint4*)E_shb;
        for (int i = tid; i < RR * NN * 2 / 16; i += TPB) dst[i] = src[i];
    }
    if (tid < GB) { sA[tid] = 0.f; sB[tid] = 0.f; }
    float sPrev = 0.f, lseP = 0.f;
    __syncthreads();

    const int b_f = tid >> 6, r_f = tid & 63;
    const int m_f = ci * RR + r_f;

    for (int t = 0; t < TT; t++) {
        float em = 0.f, pa = 0.f, easumP = 0.f;
        if (tid < 128) {
            em = __ldcg(&d_emitg[((size_t)t * BB + (b0 + b_f)) * NN + m_f]);
            if (t == 0) pa = __ldcg(&d_piadj[m_f]);
        }
        if (tid < GB && t >= 1)
            easumP = __ldcg(&d_easum[(t - 1) * BB + b0 + tid]);

        if (tid < GB) {
            float sh_t = 0.f;
            if (t >= 1) {
                float lse = sPrev + __logf(easumP);
                float d = (t >= 2) ? fminf(20.f, fmaxf(-40.f, lse - lseP)) : 0.f;
                sh_t = lse + d;
                lseP = lse;
            }
            sA[tid] = sPrev; sB[tid] = sh_t; sPrev = sh_t;
        }

        if (t > 0) {
            cp_async16(ea_smem + (unsigned)tid * 16,
                       (const char*)d_eag[(t - 1) & 1] + b0 * NN * 2 + tid * 16);
            asm volatile("cp.async.commit_group;");
            asm volatile("cp.async.wait_group 0;");
            __syncthreads();

            unsigned long long acc[8][GB];
#pragma unroll
            for (int j = 0; j < 8; j++)
#pragma unroll
                for (int k = 0; k < GB; k++) acc[j][k] = 0ull;
#pragma unroll
            for (int c = 0; c < 4; c++) {
                int n0 = c * 256 + lane * 8;
                uint4 av0 = *(const uint4*)(ea_sh + n0 * 2);
                uint4 av1 = *(const uint4*)(ea_sh + (NN + n0) * 2);
                unsigned long long a0[4], a1[4];
                a0[0] = bf2f32x2(av0.x); a0[1] = bf2f32x2(av0.y);
                a0[2] = bf2f32x2(av0.z); a0[3] = bf2f32x2(av0.w);
                a1[0] = bf2f32x2(av1.x); a1[1] = bf2f32x2(av1.y);
                a1[2] = bf2f32x2(av1.z); a1[3] = bf2f32x2(av1.w);
#pragma unroll
                for (int j = 0; j < 8; j++) {
                    uint4 ev = *(const uint4*)
                        (E_shb + ((w * 8 + j) * NN + n0) * 2);
                    unsigned long long e0 = bf2f32x2(ev.x), e1 = bf2f32x2(ev.y);
                    unsigned long long e2 = bf2f32x2(ev.z), e3 = bf2f32x2(ev.w);
                    acc[j][0] = ffma2(e0, a0[0], acc[j][0]);
                    acc[j][0] = ffma2(e1, a0[1], acc[j][0]);
                    acc[j][0] = ffma2(e2, a0[2], acc[j][0]);
                    acc[j][0] = ffma2(e3, a0[3], acc[j][0]);
                    acc[j][1] = ffma2(e0, a1[0], acc[j][1]);
                    acc[j][1] = ffma2(e1, a1[1], acc[j][1]);
                    acc[j][1] = ffma2(e2, a1[2], acc[j][1]);
                    acc[j][1] = ffma2(e3, a1[3], acc[j][1]);
                }
            }
            float r[8][GB];
#pragma unroll
            for (int j = 0; j < 8; j++)
#pragma unroll
                for (int k = 0; k < GB; k++) {
                    float2 f = *(float2*)&acc[j][k];
                    r[j][k] = f.x + f.y;
                }
#pragma unroll
            for (int off = 16; off; off >>= 1)
#pragma unroll
                for (int j = 0; j < 8; j++)
#pragma unroll
                    for (int k = 0; k < GB; k++)
                        r[j][k] += __shfl_xor_sync(0xffffffffu, r[j][k], off);
            if (lane == 0) {
#pragma unroll
                for (int j = 0; j < 8; j++)
#pragma unroll
                    for (int k = 0; k < GB; k++)
                        alpha_sh[(w * 8 + j) * GB + k] = r[j][k];
            }
        }
        __syncthreads();

        if (tid < 128) {
            float A = (t == 0)
                ? (em + pa)
                : (em + sA[b_f] + __logf(alpha_sh[r_f * GB + b_f]));
            float e = __expf(A - sB[b_f]);
            float e1 = __shfl_down_sync(0xffffffffu, e, 1);
            if (!(tid & 1)) {
                unsigned* dst = (unsigned*)
                    ((char*)d_eag[t & 1] + ((b0 + b_f) * NN + ci * RR + r_f) * 2);
                *dst = bf16x2pack(e, e1);
            }
            float sm = e;
#pragma unroll
            for (int off = 16; off; off >>= 1)
                sm += __shfl_xor_sync(0xffffffffu, sm, off);
            if (lane == 0) wsum[w] = sm;
        }
        __syncthreads();
        if (tid < GB) {
            atomicAdd(&d_easum[t * BB + b0 + tid],
                      wsum[2 * tid] + wsum[2 * tid + 1]);
            if (ci == 0) d_shift[t * BB + b0 + tid] = sB[tid];
        }
        gbar(cnt, (unsigned)(t + 1) * GSZ);
    }

    if (ci == 0 && tid < GB) {
        int b = b0 + tid;
        int tb = len[b] - 1;
        tb = tb < 0 ? 0 : (tb > TT - 1 ? TT - 1 : tb);
        out[b] = __ldcg(&d_shift[tb * BB + b]) +
                 __logf(__ldcg(&d_easum[tb * BB + b]));
    }
}

// ---------------- launch ----------------
extern "C" void kernel_launch(void* const* d_in, const int* in_sizes, int n_in,
                              void* d_out, int out_size) {
    (void)in_sizes; (void)n_in; (void)out_size;
    const float* emis  = (const float*)d_in[0];  // (N, V)
    const float* trans = (const float*)d_in[1];  // (N, N)
    const float* pri   = (const float*)d_in[2];  // (N,)
    const int*   x     = (const int*)d_in[3];    // (B, T)
    const int*   len   = (const int*)d_in[4];    // (B,)
    float*       out   = (float*)d_out;          // (B, 1)

    k_rowlse<<<NN, TPB>>>(emis);
    k_collse<<<NN / 32, dim3(32, 8)>>>(trans);
    k_prepT<<<NN, TPB>>>(trans);
    k_init<<<16, TPB>>>(pri);
    k_gather<<<TT, TPB>>>(emis, x);

    // primary: 16-CTA cluster kernel; fallback: proven grid-barrier kernel
    cudaFuncSetAttribute(k_fwd_cl, cudaFuncAttributeMaxDynamicSharedMemorySize,
                         CL_SMEM);
    cudaFuncSetAttribute(k_fwd_cl,
                         cudaFuncAttributeNonPortableClusterSizeAllowed, 1);

    cudaLaunchConfig_t cfg = {};
    cfg.gridDim  = {GG, 1, 1};
    cfg.blockDim = {TPB, 1, 1};
    cfg.dynamicSmemBytes = CL_SMEM;
    cfg.stream = 0;
    cudaLaunchAttribute attrs[1];
    attrs[0].id = cudaLaunchAttributeClusterDimension;
    attrs[0].val.clusterDim = {GSZ, 1, 1};
    cfg.attrs = attrs;
    cfg.numAttrs = 1;

    int maxClusters = 0;
    cudaError_t pe = cudaOccupancyMaxActiveClusters(&maxClusters, k_fwd_cl, &cfg);
    (void)cudaGetLastError();   // clear any probe error state

    if (pe == cudaSuccess && maxClusters >= NGRP) {
        cudaLaunchKernelEx(&cfg, k_fwd_cl, len, out);
    } else {
        cudaFuncSetAttribute(k_fwd_fb,
                             cudaFuncAttributeMaxDynamicSharedMemorySize, FB_SMEM);
        k_fwd_fb<<<GG, TPB, FB_SMEM>>>(len, out);
    }
}

// round 9
// speedup vs baseline: 1.1275x; 1.1275x over previous
#include <cuda_runtime.h>
#include <math_constants.h>

#define NN  1024
#define VV  32000
#define BB  16
#define TT  128
#define GG  128            // CTAs in forward kernel (all co-resident)
#define RR  (NN/GG)        // 8 rows of E_T per CTA
#define TPB 256

// ---------------- device scratch (static; no runtime alloc) ----------------
__device__ unsigned short d_ETh[NN*NN];       // bf16 exp(log_T' - rowmax), 2 MB
__device__ float          d_rowmax[NN];
__device__ float          d_rowlse[NN];
__device__ float          d_collse[NN];
__device__ float          d_piadj[NN];        // log_pi - rowmax
__device__ float          d_emitg[TT*NN*BB];  // emit - rowlse + rowmax, [t][m][b]
__device__ unsigned short d_eag[2][BB*NN];    // bf16 exp(alpha - shift), ping-pong
__device__ float          d_easum[TT*BB];     // sum_n ea per (t,b)
__device__ float          d_shift[TT*BB];     // shift used per (t,b)
__device__ unsigned       d_barcnt;           // grid barrier counter

// ---------------- helpers ----------------
__device__ __forceinline__ unsigned long long ffma2(
    unsigned long long a, unsigned long long b, unsigned long long c) {
    unsigned long long d;
    asm("fma.rn.f32x2 %0, %1, %2, %3;" : "=l"(d) : "l"(a), "l"(b), "l"(c));
    return d;
}
// bf16 pair (packed u32, lo = element 0) -> f32x2 (64-bit reg pair)
__device__ __forceinline__ unsigned long long bf2f32x2(unsigned u) {
    unsigned lo = u << 16, hi = u & 0xffff0000u;
    unsigned long long p;
    asm("mov.b64 %0, {%1,%2};" : "=l"(p) : "r"(lo), "r"(hi));
    return p;
}
__device__ __forceinline__ void cp_async16(unsigned dst_smem, const void* src) {
    asm volatile("cp.async.cg.shared.global [%0], [%1], 16;"
                 :: "r"(dst_smem), "l"(src));
}
__device__ __forceinline__ unsigned bf16x2pack(float lo, float hi) {
    unsigned r;
    asm("cvt.rn.bf16x2.f32 %0, %1, %2;" : "=r"(r) : "f"(hi), "f"(lo));
    return r;
}

// lightweight grid barrier: release-arrive + acquire-spin (exact R4 pattern)
__device__ __forceinline__ void gbar(unsigned target) {
    __syncthreads();
    if (threadIdx.x == 0) {
        asm volatile("red.release.gpu.add.u32 [%0], 1;" :: "l"(&d_barcnt));
        unsigned v;
        do {
            asm volatile("ld.acquire.gpu.u32 %0, [%1];" : "=r"(v) : "l"(&d_barcnt));
        } while (v < target);
    }
    __syncthreads();
}

// ---------------- prep kernel 1: rowlse (blocks 0..1023) + collse (1024..1055)
__global__ void k_pre1(const float* __restrict__ emis,
                       const float* __restrict__ trans) {
    if (blockIdx.x < NN) {
        // row logsumexp of emission
        int n = blockIdx.x;
        const float* row = emis + (size_t)n * VV;
        float mx = -CUDART_INF_F, s = 0.f;
        for (int i = threadIdx.x; i < VV; i += TPB) {
            float v = row[i];
            if (v > mx) { s = s * __expf(mx - v) + 1.f; mx = v; }
            else        { s += __expf(v - mx); }
        }
        __shared__ float smx[TPB], ss[TPB];
        smx[threadIdx.x] = mx; ss[threadIdx.x] = s;
        __syncthreads();
        for (int off = TPB / 2; off; off >>= 1) {
            if (threadIdx.x < off) {
                float m1 = smx[threadIdx.x], s1 = ss[threadIdx.x];
                float m2 = smx[threadIdx.x + off], s2 = ss[threadIdx.x + off];
                float m = fmaxf(m1, m2);
                ss[threadIdx.x]  = s1 * __expf(m1 - m) + s2 * __expf(m2 - m);
                smx[threadIdx.x] = m;
            }
            __syncthreads();
        }
        if (threadIdx.x == 0) d_rowlse[n] = smx[0] + __logf(ss[0]);
    } else {
        // column logsumexp of transition (dim 0), 32 cols per block
        int tx = threadIdx.x & 31, ty = threadIdx.x >> 5;   // 32 x 8
        int col = (blockIdx.x - NN) * 32 + tx;
        float mx = -CUDART_INF_F, s = 0.f;
        for (int m = ty; m < NN; m += 8) {
            float v = trans[m * NN + col];
            if (v > mx) { s = s * __expf(mx - v) + 1.f; mx = v; }
            else        { s += __expf(v - mx); }
        }
        __shared__ float cmx[8][32], cs[8][32];
        cmx[ty][tx] = mx; cs[ty][tx] = s;
        __syncthreads();
        if (ty == 0) {
            float m1 = mx, s1 = s;
            for (int j = 1; j < 8; j++) {
                float m2 = cmx[j][tx], s2 = cs[j][tx];
                float m = fmaxf(m1, m2);
                s1 = s1 * __expf(m1 - m) + s2 * __expf(m2 - m);
                m1 = m;
            }
            d_collse[col] = m1 + __logf(s1);
        }
    }
}

// ---------------- prep kernel 2: rowmax + bf16 E_T ----------------
__global__ void k_prepT(const float* __restrict__ trans) {
    int m = blockIdx.x;
    const float* rowp = trans + (size_t)m * NN;
    float mx = -CUDART_INF_F;
    for (int n = threadIdx.x; n < NN; n += TPB)
        mx = fmaxf(mx, rowp[n] - d_collse[n]);
    __shared__ float smx[TPB];
    smx[threadIdx.x] = mx; __syncthreads();
    for (int off = TPB / 2; off; off >>= 1) {
        if (threadIdx.x < off)
            smx[threadIdx.x] = fmaxf(smx[threadIdx.x], smx[threadIdx.x + off]);
        __syncthreads();
    }
    float rm = smx[0];
    if (threadIdx.x == 0) d_rowmax[m] = rm;
    for (int n = threadIdx.x; n < NN; n += TPB) {
        float e = __expf(rowp[n] - d_collse[n] - rm);
        unsigned r;
        asm("cvt.rn.bf16x2.f32 %0, %1, %2;" : "=r"(r) : "f"(0.f), "f"(e));
        d_ETh[m * NN + n] = (unsigned short)(r & 0xffffu);
    }
}

// ---------------- prep kernel 3: gather (blocks 0..127) + init (128..143) ---
__global__ void k_pre3(const float* __restrict__ emis,
                       const int* __restrict__ x,
                       const float* __restrict__ pri) {
    if (blockIdx.x < TT) {
        // emitg[t][m][b] = emission[m, x[b,t]] - rowlse[m] + rowmax[m]
        int t = blockIdx.x;
        __shared__ int tok[BB];
        if (threadIdx.x < BB) tok[threadIdx.x] = x[threadIdx.x * TT + t];
        __syncthreads();
        float* dst = d_emitg + (size_t)t * NN * BB;
        for (int i = threadIdx.x; i < NN * BB; i += TPB) {
            int m = i >> 4, b = i & 15;
            dst[i] = __ldg(&emis[(size_t)m * VV + tok[b]])
                     - d_rowlse[m] + d_rowmax[m];
        }
    } else {
        int j = blockIdx.x - TT;   // 0..15
        if (threadIdx.x < 128) d_easum[j * 128 + threadIdx.x] = 0.f;
        if (j == 0) {
            if (threadIdx.x == 0) d_barcnt = 0u;
            float mx = -CUDART_INF_F, s = 0.f;
            for (int i = threadIdx.x; i < NN; i += TPB) {
                float v = pri[i];
                if (v > mx) { s = s * __expf(mx - v) + 1.f; mx = v; }
                else        { s += __expf(v - mx); }
            }
            __shared__ float smx[TPB], ss[TPB];
            smx[threadIdx.x] = mx; ss[threadIdx.x] = s;
            __syncthreads();
            for (int off = TPB / 2; off; off >>= 1) {
                if (threadIdx.x < off) {
                    float m1 = smx[threadIdx.x], s1 = ss[threadIdx.x];
                    float m2 = smx[threadIdx.x + off], s2 = ss[threadIdx.x + off];
                    float m = fmaxf(m1, m2);
                    ss[threadIdx.x]  = s1 * __expf(m1 - m) + s2 * __expf(m2 - m);
                    smx[threadIdx.x] = m;
                }
                __syncthreads();
            }
            __shared__ float lp;
            if (threadIdx.x == 0) lp = smx[0] + __logf(ss[0]);
            __syncthreads();
            for (int m = threadIdx.x; m < NN; m += TPB)
                d_piadj[m] = pri[m] - lp - d_rowmax[m];
        }
    }
}

// ---------------- persistent forward recursion (exact R4 = 538us kernel) ----
// smem: E bf16 16KB + ea bf16 32KB + alpha partials (2x128) + ea temp (128)
#define FWD_SMEM (RR*NN*2 + BB*NN*2 + (2*RR*BB + RR*BB)*4)

__global__ void __launch_bounds__(TPB, 1)
k_forward(const int* __restrict__ len, float* __restrict__ out) {
    extern __shared__ char sh[];
    char*  E_shb    = sh;                            // [RR][NN] bf16, 16KB
    char*  ea_sh    = sh + RR * NN * 2;              // [BB][NN] bf16, 32KB
    float* alpha_sh = (float*)(ea_sh + BB * NN * 2); // [2][RR*BB] partials
    float* eat_sh   = alpha_sh + 2 * RR * BB;        // [RR*BB]
    __shared__ float sA[BB], sB[BB];                 // shift(t-1), shift(t)

    const int g = blockIdx.x, tid = threadIdx.x;
    const int w = tid >> 5, lane = tid & 31;
    const int nh = w >> 2;                 // n-half: warps 0-3 -> 0, 4-7 -> 1
    const int mt = w & 1, bt = (w >> 1) & 1;
    const int ltid = tid & 127;
    const unsigned ea_smem = (unsigned)__cvta_generic_to_shared(ea_sh);

    // stage E_T slice (bf16, 16KB) once
    {
        const uint4* src = (const uint4*)(d_ETh + (size_t)g * RR * NN);
        uint4* dst = (uint4*)E_shb;
        for (int i = tid; i < RR * NN * 2 / 16; i += TPB) dst[i] = src[i];
    }
    if (tid < BB) { sA[tid] = 0.f; sB[tid] = 0.f; }
    float lseP = 0.f, sPrev = 0.f;                   // tid<16 state
    __syncthreads();

    const int ml_f = tid >> 4, b_f = tid & 15, m_f = g * RR + ml_f;

    for (int t = 0; t < TT; t++) {
        // prefetches: emit term + easum(t-1) (final since barrier t-1)
        float em = 0.f, pa = 0.f, easumP = 0.f;
        if (tid < RR * BB) {
            em = __ldcg(&d_emitg[((size_t)t * NN + m_f) * BB + b_f]);
            if (t == 0) pa = __ldcg(&d_piadj[m_f]);
        }
        if (tid < BB && t >= 1)
            easumP = __ldcg(&d_easum[(t - 1) * BB + tid]);

        // -------- matvec: 2 chunks per n-half, per-half barrier pipeline ----
        if (t > 0) {
            unsigned long long acc[4][8];
#pragma unroll
            for (int j = 0; j < 4; j++)
#pragma unroll
                for (int k = 0; k < 8; k++) acc[j][k] = 0ull;
#pragma unroll
            for (int cc = 0; cc < 2; cc++) {
                if (cc == 0) asm volatile("cp.async.wait_group 1;");
                else         asm volatile("cp.async.wait_group 0;");
                asm volatile("bar.sync %0, 128;" :: "r"(2 + nh));
                int n0 = nh * 512 + cc * 256 + lane * 8;   // 8 bf16 per lane
                uint4 ev[4];
#pragma unroll
                for (int j = 0; j < 4; j++)
                    ev[j] = *(const uint4*)(E_shb + ((mt * 4 + j) * NN + n0) * 2);
                unsigned long long e[4][4];
#pragma unroll
                for (int j = 0; j < 4; j++) {
                    e[j][0] = bf2f32x2(ev[j].x); e[j][1] = bf2f32x2(ev[j].y);
                    e[j][2] = bf2f32x2(ev[j].z); e[j][3] = bf2f32x2(ev[j].w);
                }
#pragma unroll
                for (int k = 0; k < 8; k++) {
                    uint4 av = *(const uint4*)(ea_sh + ((bt * 8 + k) * NN + n0) * 2);
                    unsigned long long a0 = bf2f32x2(av.x), a1 = bf2f32x2(av.y);
                    unsigned long long a2 = bf2f32x2(av.z), a3 = bf2f32x2(av.w);
#pragma unroll
                    for (int j = 0; j < 4; j++) {
                        acc[j][k] = ffma2(e[j][0], a0, acc[j][k]);
                        acc[j][k] = ffma2(e[j][1], a1, acc[j][k]);
                        acc[j][k] = ffma2(e[j][2], a2, acc[j][k]);
                        acc[j][k] = ffma2(e[j][3], a3, acc[j][k]);
                    }
                }
            }
            float r[4][8];
#pragma unroll
            for (int j = 0; j < 4; j++)
#pragma unroll
                for (int k = 0; k < 8; k++) {
                    float2 f = *(float2*)&acc[j][k];
                    r[j][k] = f.x + f.y;
                }
#pragma unroll
            for (int off = 16; off; off >>= 1)
#pragma unroll
                for (int j = 0; j < 4; j++)
#pragma unroll
                    for (int k = 0; k < 8; k++)
                        r[j][k] += __shfl_xor_sync(0xffffffffu, r[j][k], off);
            if (lane == 0) {
#pragma unroll
                for (int j = 0; j < 4; j++)
#pragma unroll
                    for (int k = 0; k < 8; k++)
                        alpha_sh[nh * 128 + (mt * 4 + j) * BB + bt * 8 + k] = r[j][k];
            }
        }

        // -------- shift(t) from lse(t-1) (prefetched easum) --------
        if (tid < BB) {
            float sh_t;
            if (t == 0) sh_t = 0.f;
            else {
                float lse = sPrev + __logf(easumP);          // lse(t-1)
                float d = (t == 1) ? 0.f
                                   : fminf(20.f, fmaxf(-40.f, lse - lseP));
                sh_t = lse + d;
                lseP = lse;
            }
            sA[tid] = sPrev;
            sB[tid] = sh_t;
            sPrev = sh_t;
            if (g == 0) d_shift[t * BB + tid] = sh_t;
        }
        __syncthreads();

        // -------- finalize: alpha -> ea (shifted) --------
        if (tid < RR * BB) {
            float A = (t == 0)
                ? (em + pa)
                : (em + sA[b_f] + __logf(alpha_sh[tid] + alpha_sh[128 + tid]));
            eat_sh[tid] = __expf(A - sB[b_f]);
        }
        __syncthreads();

        // pack bf16 pairs -> d_eag[t&1]
        if (tid < 64) {
            int b = tid >> 2, q = tid & 3;
            float e0 = eat_sh[(2 * q) * BB + b];
            float e1 = eat_sh[(2 * q + 1) * BB + b];
            unsigned* dst = (unsigned*)&d_eag[t & 1][b * NN + g * RR + 2 * q];
            *dst = bf16x2pack(e0, e1);
        }
        // per-batch partial sums -> global
        if (tid < BB) {
            float sm = eat_sh[tid];
#pragma unroll
            for (int ml = 1; ml < RR; ml++) sm += eat_sh[ml * BB + tid];
            atomicAdd(&d_easum[t * BB + tid], sm);
        }

        gbar((unsigned)(t + 1) * GG);

        // -------- issue async reload of ea(t) for step t+1 (per half) ------
        if (t < TT - 1) {
            const char* src = (const char*)d_eag[t & 1];
#pragma unroll
            for (int cc = 0; cc < 2; cc++) {
#pragma unroll
                for (int k = 0; k < 4; k++) {
                    int idx = ltid + 128 * k;        // [0,512) 16B units
                    int b = idx >> 5, o = idx & 31;
                    unsigned off =
                        (unsigned)(b * (NN * 2) + nh * 1024 + cc * 512 + o * 16);
                    cp_async16(ea_smem + off, src + off);
                }
                asm volatile("cp.async.commit_group;");
            }
        }
    }

    // final output: out[b] = shift[len-1] + log(easum[len-1])
    if (g == 0 && tid < BB) {
        int tb = len[tid] - 1;
        tb = tb < 0 ? 0 : (tb > TT - 1 ? TT - 1 : tb);
        out[tid] = d_shift[tb * BB + tid] + __logf(__ldcg(&d_easum[tb * BB + tid]));
    }
}

// ---------------- launch: exactly 4 kernels so ncu's slot #4 = k_forward ----
extern "C" void kernel_launch(void* const* d_in, const int* in_sizes, int n_in,
                              void* d_out, int out_size) {
    (void)in_sizes; (void)n_in; (void)out_size;
    const float* emis  = (const float*)d_in[0];  // (N, V)
    const float* trans = (const float*)d_in[1];  // (N, N)
    const float* pri   = (const float*)d_in[2];  // (N,)
    const int*   x     = (const int*)d_in[3];    // (B, T)
    const int*   len   = (const int*)d_in[4];    // (B,)
    float*       out   = (float*)d_out;          // (B, 1)

    cudaFuncSetAttribute(k_forward, cudaFuncAttributeMaxDynamicSharedMemorySize,
                         FWD_SMEM);

    k_pre1<<<NN + NN / 32, TPB>>>(emis, trans);   // rowlse + collse
    k_prepT<<<NN, TPB>>>(trans);                  // rowmax + bf16 E_T
    k_pre3<<<TT + 16, TPB>>>(emis, x, pri);       // gather + init
    k_forward<<<GG, TPB, FWD_SMEM>>>(len, out);   // launch #4
}